// round 16
// baseline (speedup 1.0000x reference)
#include <cuda_runtime.h>
#include <cuda_fp16.h>
#include <math.h>
#include <stdint.h>

#define H 1024
#define BB 16384
#define NSTEPS 8
// fused N layout: [ op1:0..1023 | num1:1024..2047 | gates interleaved: n=2048+4*j+g, g=(r,z,in,hn) ]
#define NB 6144

// GEMM tiling: CTA 128x128 (256 thr, 8 warps of 64x32), BK=64, 3 stages, 2 CTA/SM
#define BM 128
#define BN 128
#define BK 64
#define STAGES 3
#define TILE_A 16384                // A tile: 128 rows x 64 fp16
#define STAGE_B (2 * TILE_A)        // 32768 (A | B)
#define GEMM_SMEM (STAGES * STAGE_B)   // 98304
#define NTILES ((NB / BN) * (BB / BM))  // 6144
#define TILES_X (NB / BN)               // 48

// ---- scratch (device globals: sanctioned no-alloc workaround) ----
__device__ __half g_B[(size_t)NB * H];      // 12 MB  W_big fp16, [n][k]
__device__ __half g_A0[(size_t)BB * H];     // 32 MB  h fp16 ping
__device__ __half g_A1[(size_t)BB * H];     // 32 MB  h fp16 pong
__device__ float g_bias[NB];
__device__ float g_part[NSTEPS][8][(size_t)BB * 5];  // 21 MB  op partials (step, 128-col chunk)
__device__ float g_pnum[NSTEPS][8][(size_t)BB];      // 4.2 MB num partials
__device__ unsigned int g_bar[NSTEPS];               // inter-step barrier counters

// ================= helpers =================
__device__ __forceinline__ uint32_t smem_u32(const void* p) {
    uint32_t a;
    asm("{ .reg .u64 t; cvta.to.shared.u64 t, %1; cvt.u32.u64 %0, t; }" : "=r"(a) : "l"(p));
    return a;
}
__device__ __forceinline__ void cpasync16(uint32_t s, const void* g) {
    asm volatile("cp.async.cg.shared.global [%0], [%1], 16;" :: "r"(s), "l"(g) : "memory");
}
__device__ __forceinline__ void cp_commit() {
    asm volatile("cp.async.commit_group;" ::: "memory");
}
__device__ __forceinline__ void cp_wait1() {
    asm volatile("cp.async.wait_group 1;" ::: "memory");
}
__device__ __forceinline__ void cp_wait0() {
    asm volatile("cp.async.wait_group 0;" ::: "memory");
}
__device__ __forceinline__ void ldsm4(uint32_t a, uint32_t& r0, uint32_t& r1, uint32_t& r2, uint32_t& r3) {
    asm volatile("ldmatrix.sync.aligned.m8n8.x4.shared.b16 {%0,%1,%2,%3}, [%4];"
                 : "=r"(r0), "=r"(r1), "=r"(r2), "=r"(r3) : "r"(a));
}
__device__ __forceinline__ void mma16816(float* c, const uint32_t* a, const uint32_t* b) {
    asm volatile("mma.sync.aligned.m16n8k16.row.col.f32.f16.f16.f32 "
                 "{%0,%1,%2,%3}, {%4,%5,%6,%7}, {%8,%9}, {%0,%1,%2,%3};"
                 : "+f"(c[0]), "+f"(c[1]), "+f"(c[2]), "+f"(c[3])
                 : "r"(a[0]), "r"(a[1]), "r"(a[2]), "r"(a[3]), "r"(b[0]), "r"(b[1]));
}
// swizzled byte offset within a 64-fp16-wide tile (128B rows, 8x16B units)
__device__ __forceinline__ uint32_t SW(uint32_t row, uint32_t u) {
    return row * 128u + ((u ^ (row & 7u)) << 4);
}
__device__ __forceinline__ float gelu_f(float x) {
    return 0.5f * x * (1.0f + erff(x * 0.70710678118654752440f));
}
__device__ __forceinline__ float sigmoid_f(float x) {
    return 1.0f / (1.0f + expf(-x));
}
__device__ __forceinline__ uint32_t pkh2(float a, float b) {
    __half2 t = __floats2half2_rn(a, b);
    return *reinterpret_cast<uint32_t*>(&t);
}
__device__ __forceinline__ float qsum(float v) {   // reduce over lane&3 group
    v += __shfl_xor_sync(0xffffffffu, v, 1);
    v += __shfl_xor_sync(0xffffffffu, v, 2);
    return v;
}

// ================= prep: fused weights -> fp16 + x -> fp16 A0 + barrier reset ========
__global__ void prep_kernel(const float* __restrict__ w_op1, const float* __restrict__ b_op1,
                            const float* __restrict__ w_num1, const float* __restrict__ b_num1,
                            const float* __restrict__ w_ih, const float* __restrict__ b_ih,
                            const float* __restrict__ w_hh, const float* __restrict__ b_hh,
                            const float* __restrict__ x) {
    int idx = blockIdx.x * blockDim.x + threadIdx.x;
    if (idx < NSTEPS) g_bar[idx] = 0u;
    if (idx < NB * H) {
        int n = idx >> 10;
        int k = idx & 1023;
        float v;
        float bb = 0.f;
        if (n < 1024) {
            v = w_op1[k * H + n];
            bb = b_op1[n];
        } else if (n < 2048) {
            v = w_num1[k * H + (n - 1024)];
            bb = b_num1[n - 1024];
        } else {
            int j = (n - 2048) >> 2;
            int g = n & 3;
            if (g == 0) {
                v = w_ih[(size_t)j * H + k] + w_hh[(size_t)j * H + k];
                bb = b_ih[j] + b_hh[j];
            } else if (g == 1) {
                v = w_ih[(size_t)(H + j) * H + k] + w_hh[(size_t)(H + j) * H + k];
                bb = b_ih[H + j] + b_hh[H + j];
            } else if (g == 2) {
                v = w_ih[(size_t)(2 * H + j) * H + k];
                bb = b_ih[2 * H + j];
            } else {
                v = w_hh[(size_t)(2 * H + j) * H + k];
                bb = b_hh[2 * H + j];
            }
        }
        g_B[idx] = __float2half(v);
        if (k == 0) g_bias[n] = bb;
    } else {
        int t = idx - NB * H;                  // over BB*H/4
        if (t < BB * H / 4) {
            float4 v = *(const float4*)(x + (size_t)t * 4);
            *(uint2*)(g_A0 + (size_t)t * 4) = make_uint2(pkh2(v.x, v.y), pkh2(v.z, v.w));
        }
    }
}

// ================= one 128x128 output tile (mainloop + fused epilogue) =================
__device__ __forceinline__ void process_tile(
    char* smem, uint32_t sb, int step, int bx, int by,
    const float* __restrict__ hin, float* __restrict__ hout,
    const __half* __restrict__ Ain, __half* __restrict__ Aout,
    const float* __restrict__ w_op2, const float* __restrict__ w_num2)
{
    int tid = threadIdx.x;
    int lane = tid & 31;
    int wid = tid >> 5;
    int warp_m = wid & 1;
    int warp_n = wid >> 1;
    int m0 = by * BM;
    int n0 = bx * BN;

    __syncthreads();   // smem reuse fence vs previous tile's epilogue

    int row0 = tid >> 3;
    int u0 = tid & 7;
    uint32_t so = SW((uint32_t)row0, (uint32_t)u0);
    const __half* pA0 = Ain + (size_t)(m0 + row0) * H + u0 * 8;
    const __half* pB0 = g_B + (size_t)(n0 + row0) * H + u0 * 8;

    uint32_t rA = (uint32_t)(warp_m * 64 + (lane & 15));
    uint32_t baseA = rA * 128u;
    uint32_t hib = (uint32_t)(lane >> 4);
    uint32_t mAx = rA & 7u;
    uint32_t rB = (uint32_t)(warp_n * 32 + (lane & 7) + ((lane >> 4) << 3));
    uint32_t baseB = rB * 128u;
    uint32_t bbit = (uint32_t)((lane >> 3) & 1);
    uint32_t mBx = rB & 7u;
    uint32_t xA[4], xB[4];
    #pragma unroll
    for (int ks = 0; ks < 4; ks++) {
        xA[ks] = (((uint32_t)(ks * 2) + hib) ^ mAx) << 4;
        xB[ks] = (((uint32_t)(ks * 2) + bbit) ^ mBx) << 4;
    }

    float acc[4][4][4];
    #pragma unroll
    for (int i = 0; i < 4; i++)
        #pragma unroll
        for (int j = 0; j < 4; j++)
            #pragma unroll
            for (int r = 0; r < 4; r++) acc[i][j][r] = 0.f;

    #define ISSUE(kb, stg) do {                                                   \
        uint32_t base = sb + (stg) * STAGE_B;                                     \
        int ko = (kb) * BK;                                                       \
        _Pragma("unroll")                                                         \
        for (int i = 0; i < 4; i++)                                               \
            cpasync16(base + so + i * 4096u, pA0 + (size_t)(i * 32) * H + ko);    \
        _Pragma("unroll")                                                         \
        for (int i = 0; i < 4; i++)                                               \
            cpasync16(base + TILE_A + so + i * 4096u,                             \
                      pB0 + (size_t)(i * 32) * H + ko);                           \
        cp_commit();                                                              \
    } while (0)

    ISSUE(0, 0);
    ISSUE(1, 1);
    cp_wait1();
    __syncthreads();

    const int NKB = H / BK;   // 16
    #pragma unroll
    for (int kb = 0; kb < NKB; kb++) {
        if (kb + 2 < NKB) ISSUE(kb + 2, (kb + 2) % STAGES);

        uint32_t base = sb + (uint32_t)(kb % STAGES) * STAGE_B;
        uint32_t sA = base + baseA;
        uint32_t sB = base + TILE_A + baseB;

        #pragma unroll
        for (int ks = 0; ks < 4; ks++) {
            uint32_t Af[4][4], Bf[4][2];
            #pragma unroll
            for (int nj2 = 0; nj2 < 2; nj2++)
                ldsm4(sB + nj2 * 2048 + xB[ks], Bf[nj2 * 2][0], Bf[nj2 * 2][1],
                      Bf[nj2 * 2 + 1][0], Bf[nj2 * 2 + 1][1]);
            #pragma unroll
            for (int mi = 0; mi < 4; mi++)
                ldsm4(sA + mi * 2048 + xA[ks], Af[mi][0], Af[mi][1], Af[mi][2], Af[mi][3]);
            #pragma unroll
            for (int mi = 0; mi < 4; mi++)
                #pragma unroll
                for (int nj = 0; nj < 4; nj++)
                    mma16816(acc[mi][nj], Af[mi], Bf[nj]);
        }
        if (kb + 1 < NKB) {
            if (kb + 2 < NKB) cp_wait1(); else cp_wait0();
            __syncthreads();
        }
    }
    __syncthreads();

    if (n0 < 1024) {
        float* sw = (float*)smem;
        float* red = (float*)(smem + 4096);
        for (int i = tid; i < 128 * 5; i += 256) sw[i] = w_op2[(size_t)(n0 + i / 5) * 5 + (i % 5)];
        __syncthreads();
        #pragma unroll
        for (int mi = 0; mi < 4; mi++)
            #pragma unroll
            for (int half = 0; half < 2; half++) {
                float s0 = 0.f, s1 = 0.f, s2 = 0.f, s3 = 0.f, s4 = 0.f;
                #pragma unroll
                for (int nj = 0; nj < 4; nj++) {
                    int nl = warp_n * 32 + nj * 8 + (lane & 3) * 2;
                    float2 b2 = *(const float2*)&g_bias[n0 + nl];
                    float v0 = gelu_f(acc[mi][nj][half * 2 + 0] + b2.x);
                    float v1 = gelu_f(acc[mi][nj][half * 2 + 1] + b2.y);
                    const float* w0 = &sw[nl * 5];
                    const float* w1 = &sw[(nl + 1) * 5];
                    s0 += v0 * w0[0] + v1 * w1[0];
                    s1 += v0 * w0[1] + v1 * w1[1];
                    s2 += v0 * w0[2] + v1 * w1[2];
                    s3 += v0 * w0[3] + v1 * w1[3];
                    s4 += v0 * w0[4] + v1 * w1[4];
                }
                s0 = qsum(s0); s1 = qsum(s1); s2 = qsum(s2); s3 = qsum(s3); s4 = qsum(s4);
                if ((lane & 3) == 0) {
                    int rl = warp_m * 64 + mi * 16 + (lane >> 2) + half * 8;
                    float* d = &red[(rl * 4 + warp_n) * 5];
                    d[0] = s0; d[1] = s1; d[2] = s2; d[3] = s3; d[4] = s4;
                }
            }
        __syncthreads();
        if (tid < 128) {
            int chunk = n0 >> 7;
            float o0 = 0.f, o1 = 0.f, o2 = 0.f, o3 = 0.f, o4 = 0.f;
            #pragma unroll
            for (int wn = 0; wn < 4; wn++) {
                const float* p = &red[(tid * 4 + wn) * 5];
                o0 += p[0]; o1 += p[1]; o2 += p[2]; o3 += p[3]; o4 += p[4];
            }
            float* d = &g_part[step][chunk][(size_t)(m0 + tid) * 5];
            d[0] = o0; d[1] = o1; d[2] = o2; d[3] = o3; d[4] = o4;
        }
    } else if (n0 < 2048) {
        float* sw = (float*)smem;
        float* red = (float*)(smem + 1024);
        for (int i = tid; i < 128; i += 256) sw[i] = w_num2[n0 - 1024 + i];
        __syncthreads();
        #pragma unroll
        for (int mi = 0; mi < 4; mi++)
            #pragma unroll
            for (int half = 0; half < 2; half++) {
                float s = 0.f;
                #pragma unroll
                for (int nj = 0; nj < 4; nj++) {
                    int nl = warp_n * 32 + nj * 8 + (lane & 3) * 2;
                    float2 b2 = *(const float2*)&g_bias[n0 + nl];
                    float v0 = gelu_f(acc[mi][nj][half * 2 + 0] + b2.x);
                    float v1 = gelu_f(acc[mi][nj][half * 2 + 1] + b2.y);
                    s += v0 * sw[nl] + v1 * sw[nl + 1];
                }
                s = qsum(s);
                if ((lane & 3) == 0) {
                    int rl = warp_m * 64 + mi * 16 + (lane >> 2) + half * 8;
                    red[rl * 4 + warp_n] = s;
                }
            }
        __syncthreads();
        if (tid < 128) {
            int chunk = (n0 - 1024) >> 7;
            float s = red[tid * 4] + red[tid * 4 + 1] + red[tid * 4 + 2] + red[tid * 4 + 3];
            g_pnum[step][chunk][m0 + tid] = s;
        }
    } else {
        int j0g = (n0 - 2048) >> 2;
        float* sh_hold = (float*)smem;
        float* sh_hnew = (float*)(smem + 17024);

        #pragma unroll
        for (int it = 0; it < 4; it++) {
            int i4 = tid + it * 256;
            int r = i4 >> 3;
            int c4 = i4 & 7;
            float4 v = *(const float4*)(hin + (size_t)(m0 + r) * H + j0g + c4 * 4);
            float* d = &sh_hold[r * 33 + c4 * 4];
            d[0] = v.x; d[1] = v.y; d[2] = v.z; d[3] = v.w;
        }
        __syncthreads();

        bool compute = ((lane & 1) == 0);
        int jbase = warp_n * 8 + ((lane & 3) >> 1);
        int mbase = warp_m * 64 + (lane >> 2);
        #pragma unroll
        for (int nj = 0; nj < 4; nj++) {
            int n = n0 + warp_n * 32 + nj * 8 + (lane & 3) * 2;
            float2 b2 = *(const float2*)&g_bias[n];
            #pragma unroll
            for (int mi = 0; mi < 4; mi++) {
                float c0 = acc[mi][nj][0] + b2.x;
                float c1 = acc[mi][nj][1] + b2.y;
                float c2 = acc[mi][nj][2] + b2.x;
                float c3 = acc[mi][nj][3] + b2.y;
                float p0 = __shfl_xor_sync(0xffffffffu, c0, 1);
                float p1 = __shfl_xor_sync(0xffffffffu, c1, 1);
                float p2 = __shfl_xor_sync(0xffffffffu, c2, 1);
                float p3 = __shfl_xor_sync(0xffffffffu, c3, 1);
                if (compute) {
                    int jl = jbase + nj * 2;
                    int ml = mbase + mi * 16;
                    float rr = sigmoid_f(c0);
                    float zz = sigmoid_f(c1);
                    float nn = tanhf(p0 + rr * p1);
                    sh_hnew[ml * 33 + jl] = (1.f - zz) * nn + zz * sh_hold[ml * 33 + jl];
                    float rr2 = sigmoid_f(c2);
                    float zz2 = sigmoid_f(c3);
                    float nn2 = tanhf(p2 + rr2 * p3);
                    sh_hnew[(ml + 8) * 33 + jl] =
                        (1.f - zz2) * nn2 + zz2 * sh_hold[(ml + 8) * 33 + jl];
                }
            }
        }
        __syncthreads();

        #pragma unroll
        for (int it = 0; it < 4; it++) {
            int i4 = tid + it * 256;
            int r = i4 >> 3;
            int c4 = i4 & 7;
            const float* s = &sh_hnew[r * 33 + c4 * 4];
            float4 v = make_float4(s[0], s[1], s[2], s[3]);
            size_t off = (size_t)(m0 + r) * H + j0g + c4 * 4;
            *(float4*)(hout + off) = v;
            *(uint2*)(Aout + off) = make_uint2(pkh2(v.x, v.y), pkh2(v.z, v.w));
        }
    }
}

// ================= persistent kernel: all 8 steps + final head reduce =================
__global__ __launch_bounds__(256, 2) void persistent_kernel(
    float* __restrict__ states, float* __restrict__ final_state,
    const float* __restrict__ w_op2, const float* __restrict__ w_num2,
    const float* __restrict__ b_op2, const float* __restrict__ b_num2,
    float* __restrict__ ops, float* __restrict__ nums)
{
    extern __shared__ char smem[];
    uint32_t sb = smem_u32(smem);
    int bid = blockIdx.x;
    int nctas = gridDim.x;
    int tid = threadIdx.x;

    for (int s = 0; s < NSTEPS; s++) {
        const float* hin = states + (size_t)s * BB * H;
        float* hout = (s < NSTEPS - 1) ? states + (size_t)(s + 1) * BB * H : final_state;
        const __half* Ain = (s & 1) ? g_A1 : g_A0;
        __half* Aout = (s & 1) ? g_A0 : g_A1;

        for (int t = bid; t < NTILES; t += nctas) {
            int bx = t % TILES_X;
            int by = t / TILES_X;
            process_tile(smem, sb, s, bx, by, hin, hout, Ain, Aout, w_op2, w_num2);
        }

        // device-wide barrier between steps (and before final reduce)
        __syncthreads();
        if (tid == 0) {
            __threadfence();
            atomicAdd(&g_bar[s], 1u);
            while (atomicAdd(&g_bar[s], 0u) < (unsigned)nctas) { __nanosleep(128); }
            __threadfence();
        }
        __syncthreads();
    }

    // final head reduce over all steps (partitioned across all CTAs)
    float bo0 = b_op2[0], bo1 = b_op2[1], bo2 = b_op2[2], bo3 = b_op2[3], bo4 = b_op2[4];
    float bn = b_num2[0];
    for (int i = bid * 256 + tid; i < NSTEPS * BB; i += nctas * 256) {
        int s = i >> 14;        // / BB
        int b = i & (BB - 1);
        float s0 = bo0, s1 = bo1, s2 = bo2, s3 = bo3, s4 = bo4;
        float sn = bn;
        #pragma unroll
        for (int k = 0; k < 8; k++) {
            const float* p = &g_part[s][k][(size_t)b * 5];
            s0 += p[0]; s1 += p[1]; s2 += p[2]; s3 += p[3]; s4 += p[4];
            sn += g_pnum[s][k][b];
        }
        float* o = ops + (size_t)i * 5;
        o[0] = s0; o[1] = s1; o[2] = s2; o[3] = s3; o[4] = s4;
        nums[i] = sn;
    }
}

extern "C" void kernel_launch(void* const* d_in, const int* in_sizes, int n_in,
                              void* d_out, int out_size) {
    const float* x      = (const float*)d_in[0];
    const float* w_op1  = (const float*)d_in[2];
    const float* b_op1  = (const float*)d_in[3];
    const float* w_op2  = (const float*)d_in[4];
    const float* b_op2  = (const float*)d_in[5];
    const float* w_num1 = (const float*)d_in[6];
    const float* b_num1 = (const float*)d_in[7];
    const float* w_num2 = (const float*)d_in[8];
    const float* b_num2 = (const float*)d_in[9];
    const float* w_ih   = (const float*)d_in[10];
    const float* b_ih   = (const float*)d_in[11];
    const float* w_hh   = (const float*)d_in[12];
    const float* b_hh   = (const float*)d_in[13];

    float* out = (float*)d_out;
    float* final_state = out;                       // [B,H]
    float* ops    = out + (size_t)BB * H;           // [8,B,5]
    float* nums   = ops + (size_t)NSTEPS * BB * 5;  // [8,B,1]
    float* states = nums + (size_t)NSTEPS * BB;     // [8,B,H]

    static int n_sm = 0;
    if (n_sm == 0) {
        cudaDeviceGetAttribute(&n_sm, cudaDevAttrMultiProcessorCount, 0);
        cudaFuncSetAttribute(persistent_kernel,
                             cudaFuncAttributeMaxDynamicSharedMemorySize, GEMM_SMEM);
    }
    int nctas = 2 * n_sm;

    int prep_threads = NB * H + BB * H / 4;
    prep_kernel<<<(prep_threads + 255) / 256, 256>>>(w_op1, b_op1, w_num1, b_num1,
                                                     w_ih, b_ih, w_hh, b_hh, x);
    cudaMemcpyAsync(states, x, (size_t)BB * H * sizeof(float), cudaMemcpyDeviceToDevice);

    persistent_kernel<<<nctas, 256, GEMM_SMEM>>>(states, final_state, w_op2, w_num2,
                                                 b_op2, b_num2, ops, nums);
}

// round 17
// speedup vs baseline: 1.0967x; 1.0967x over previous
#include <cuda_runtime.h>
#include <cuda_fp16.h>
#include <math.h>
#include <stdint.h>

#define H 1024
#define BB 16384
#define NSTEPS 8
// fused N layout: [ op1:0..1023 | num1:1024..2047 | gates interleaved: n=2048+4*j+g, g=(r,z,in,hn) ]
#define NB 6144

// GEMM tiling: CTA 128x128 (256 thr, 8 warps of 64x32), BK=64, 3 stages, 2 CTA/SM
#define BM 128
#define BN 128
#define BK 64
#define STAGES 3
#define TILE_A 16384                // A tile: 128 rows x 64 fp16
#define STAGE_B (2 * TILE_A)        // 32768 (A | B)
#define GEMM_SMEM (STAGES * STAGE_B)   // 98304

// ---- scratch (device globals: sanctioned no-alloc workaround) ----
__device__ __half g_B[(size_t)NB * H];      // 12 MB  W_big fp16, [n][k]
__device__ __half g_A0[(size_t)BB * H];     // 32 MB  h fp16 ping
__device__ __half g_A1[(size_t)BB * H];     // 32 MB  h fp16 pong
__device__ float g_bias[NB];
__device__ float g_part[NSTEPS][8][(size_t)BB * 5];  // 21 MB  op partials (step, 128-col chunk)
__device__ float g_pnum[NSTEPS][8][(size_t)BB];      // 4.2 MB num partials

// ================= helpers =================
__device__ __forceinline__ uint32_t smem_u32(const void* p) {
    uint32_t a;
    asm("{ .reg .u64 t; cvta.to.shared.u64 t, %1; cvt.u32.u64 %0, t; }" : "=r"(a) : "l"(p));
    return a;
}
__device__ __forceinline__ void cpasync16(uint32_t s, const void* g) {
    asm volatile("cp.async.cg.shared.global [%0], [%1], 16;" :: "r"(s), "l"(g) : "memory");
}
__device__ __forceinline__ void cp_commit() {
    asm volatile("cp.async.commit_group;" ::: "memory");
}
__device__ __forceinline__ void cp_wait1() {
    asm volatile("cp.async.wait_group 1;" ::: "memory");
}
__device__ __forceinline__ void cp_wait0() {
    asm volatile("cp.async.wait_group 0;" ::: "memory");
}
__device__ __forceinline__ void ldsm4(uint32_t a, uint32_t& r0, uint32_t& r1, uint32_t& r2, uint32_t& r3) {
    asm volatile("ldmatrix.sync.aligned.m8n8.x4.shared.b16 {%0,%1,%2,%3}, [%4];"
                 : "=r"(r0), "=r"(r1), "=r"(r2), "=r"(r3) : "r"(a));
}
__device__ __forceinline__ void mma16816(float* c, const uint32_t* a, const uint32_t* b) {
    asm volatile("mma.sync.aligned.m16n8k16.row.col.f32.f16.f16.f32 "
                 "{%0,%1,%2,%3}, {%4,%5,%6,%7}, {%8,%9}, {%0,%1,%2,%3};"
                 : "+f"(c[0]), "+f"(c[1]), "+f"(c[2]), "+f"(c[3])
                 : "r"(a[0]), "r"(a[1]), "r"(a[2]), "r"(a[3]), "r"(b[0]), "r"(b[1]));
}
// swizzled byte offset within a 64-fp16-wide tile (128B rows, 8x16B units)
__device__ __forceinline__ uint32_t SW(uint32_t row, uint32_t u) {
    return row * 128u + ((u ^ (row & 7u)) << 4);
}
__device__ __forceinline__ float gelu_f(float x) {
    return 0.5f * x * (1.0f + erff(x * 0.70710678118654752440f));
}
__device__ __forceinline__ float sigmoid_f(float x) {
    return 1.0f / (1.0f + expf(-x));
}
__device__ __forceinline__ uint32_t pkh2(float a, float b) {
    __half2 t = __floats2half2_rn(a, b);
    return *reinterpret_cast<uint32_t*>(&t);
}
__device__ __forceinline__ float qsum(float v) {   // reduce over lane&3 group
    v += __shfl_xor_sync(0xffffffffu, v, 1);
    v += __shfl_xor_sync(0xffffffffu, v, 2);
    return v;
}

// ====== prep: fused weights -> fp16, x -> fp16 A0, x -> states[0] (fused copy) ======
__global__ void prep_kernel(const float* __restrict__ w_op1, const float* __restrict__ b_op1,
                            const float* __restrict__ w_num1, const float* __restrict__ b_num1,
                            const float* __restrict__ w_ih, const float* __restrict__ b_ih,
                            const float* __restrict__ w_hh, const float* __restrict__ b_hh,
                            const float* __restrict__ x, float* __restrict__ states0) {
    int idx = blockIdx.x * blockDim.x + threadIdx.x;
    if (idx < NB * H) {
        int n = idx >> 10;
        int k = idx & 1023;
        float v;
        float bb = 0.f;
        if (n < 1024) {
            v = w_op1[k * H + n];
            bb = b_op1[n];
        } else if (n < 2048) {
            v = w_num1[k * H + (n - 1024)];
            bb = b_num1[n - 1024];
        } else {
            int j = (n - 2048) >> 2;
            int g = n & 3;
            if (g == 0) {
                v = w_ih[(size_t)j * H + k] + w_hh[(size_t)j * H + k];
                bb = b_ih[j] + b_hh[j];
            } else if (g == 1) {
                v = w_ih[(size_t)(H + j) * H + k] + w_hh[(size_t)(H + j) * H + k];
                bb = b_ih[H + j] + b_hh[H + j];
            } else if (g == 2) {
                v = w_ih[(size_t)(2 * H + j) * H + k];
                bb = b_ih[2 * H + j];
            } else {
                v = w_hh[(size_t)(2 * H + j) * H + k];
                bb = b_hh[2 * H + j];
            }
        }
        g_B[idx] = __float2half(v);
        if (k == 0) g_bias[n] = bb;
    } else {
        int t = idx - NB * H;                  // over BB*H/4
        if (t < BB * H / 4) {
            float4 v = *(const float4*)(x + (size_t)t * 4);
            *(uint2*)(g_A0 + (size_t)t * 4) = make_uint2(pkh2(v.x, v.y), pkh2(v.z, v.w));
            *(float4*)(states0 + (size_t)t * 4) = v;   // fused states[0] = x
        }
    }
}

// ===== mma.sync GEMM: heads -> CTA-reduced partials; gates -> GRU update in epilogue ====
__global__ __launch_bounds__(256, 2) void gemm_mma_kernel(int step,
                                                          const float* __restrict__ hin,
                                                          float* __restrict__ hout,
                                                          const float* __restrict__ w_op2,
                                                          const float* __restrict__ w_num2) {
    extern __shared__ char smem[];
    uint32_t sb = smem_u32(smem);
    int tid = threadIdx.x;
    int lane = tid & 31;
    int wid = tid >> 5;
    int warp_m = wid & 1;     // 2 warps in M -> 64 rows each
    int warp_n = wid >> 1;    // 4 warps in N -> 32 cols each
    int m0 = blockIdx.y * BM;
    int n0 = blockIdx.x * BN;
    int rb = step & 1;

    const __half* Ain = rb ? g_A1 : g_A0;
    __half* Aout = rb ? g_A0 : g_A1;

    // g2s: per array each thread covers rows (tid>>3)+{0,32,64,96} at 16B unit tid&7
    int row0 = tid >> 3;          // 0..31
    int u0 = tid & 7;
    uint32_t so = SW((uint32_t)row0, (uint32_t)u0);
    const __half* pA0 = Ain + (size_t)(m0 + row0) * H + u0 * 8;
    const __half* pB0 = g_B + (size_t)(n0 + row0) * H + u0 * 8;

    // ldmatrix offset components
    uint32_t rA = (uint32_t)(warp_m * 64 + (lane & 15));
    uint32_t baseA = rA * 128u;
    uint32_t hib = (uint32_t)(lane >> 4);
    uint32_t mAx = rA & 7u;
    uint32_t rB = (uint32_t)(warp_n * 32 + (lane & 7) + ((lane >> 4) << 3));
    uint32_t baseB = rB * 128u;
    uint32_t bbit = (uint32_t)((lane >> 3) & 1);
    uint32_t mBx = rB & 7u;
    uint32_t xA[4], xB[4];
    #pragma unroll
    for (int ks = 0; ks < 4; ks++) {
        xA[ks] = (((uint32_t)(ks * 2) + hib) ^ mAx) << 4;
        xB[ks] = (((uint32_t)(ks * 2) + bbit) ^ mBx) << 4;
    }

    float acc[4][4][4];
    #pragma unroll
    for (int i = 0; i < 4; i++)
        #pragma unroll
        for (int j = 0; j < 4; j++)
            #pragma unroll
            for (int r = 0; r < 4; r++) acc[i][j][r] = 0.f;

    #define ISSUE(kb, stg) do {                                                   \
        uint32_t base = sb + (stg) * STAGE_B;                                     \
        int ko = (kb) * BK;                                                       \
        _Pragma("unroll")                                                         \
        for (int i = 0; i < 4; i++)                                               \
            cpasync16(base + so + i * 4096u, pA0 + (size_t)(i * 32) * H + ko);    \
        _Pragma("unroll")                                                         \
        for (int i = 0; i < 4; i++)                                               \
            cpasync16(base + TILE_A + so + i * 4096u,                             \
                      pB0 + (size_t)(i * 32) * H + ko);                           \
        cp_commit();                                                              \
    } while (0)

    ISSUE(0, 0);
    ISSUE(1, 1);
    cp_wait1();
    __syncthreads();

    const int NKB = H / BK;   // 16
    #pragma unroll
    for (int kb = 0; kb < NKB; kb++) {
        if (kb + 2 < NKB) ISSUE(kb + 2, (kb + 2) % STAGES);   // load-early into released stage

        uint32_t base = sb + (uint32_t)(kb % STAGES) * STAGE_B;
        uint32_t sA = base + baseA;
        uint32_t sB = base + TILE_A + baseB;

        #pragma unroll
        for (int ks = 0; ks < 4; ks++) {
            uint32_t Af[4][4], Bf[4][2];
            #pragma unroll
            for (int nj2 = 0; nj2 < 2; nj2++)
                ldsm4(sB + nj2 * 2048 + xB[ks], Bf[nj2 * 2][0], Bf[nj2 * 2][1],
                      Bf[nj2 * 2 + 1][0], Bf[nj2 * 2 + 1][1]);
            #pragma unroll
            for (int mi = 0; mi < 4; mi++)
                ldsm4(sA + mi * 2048 + xA[ks], Af[mi][0], Af[mi][1], Af[mi][2], Af[mi][3]);
            #pragma unroll
            for (int mi = 0; mi < 4; mi++)
                #pragma unroll
                for (int nj = 0; nj < 4; nj++)
                    mma16816(acc[mi][nj], Af[mi], Bf[nj]);
        }
        if (kb + 1 < NKB) {
            if (kb + 2 < NKB) cp_wait1(); else cp_wait0();
            __syncthreads();
        }
    }
    __syncthreads();   // mainloop smem reads done before epilogue reuses smem

    if (n0 < 1024) {
        // ---- op head epilogue: GELU + projection, CTA-reduced to 1 partial/row ----
        float* sw = (float*)smem;                 // [128][5] weights
        float* red = (float*)(smem + 4096);       // [128 rows][4 wn][5]
        for (int i = tid; i < 128 * 5; i += 256) sw[i] = w_op2[(size_t)(n0 + i / 5) * 5 + (i % 5)];
        __syncthreads();
        #pragma unroll
        for (int mi = 0; mi < 4; mi++)
            #pragma unroll
            for (int half = 0; half < 2; half++) {
                float s0 = 0.f, s1 = 0.f, s2 = 0.f, s3 = 0.f, s4 = 0.f;
                #pragma unroll
                for (int nj = 0; nj < 4; nj++) {
                    int nl = warp_n * 32 + nj * 8 + (lane & 3) * 2;
                    float2 b2 = *(const float2*)&g_bias[n0 + nl];
                    float v0 = gelu_f(acc[mi][nj][half * 2 + 0] + b2.x);
                    float v1 = gelu_f(acc[mi][nj][half * 2 + 1] + b2.y);
                    const float* w0 = &sw[nl * 5];
                    const float* w1 = &sw[(nl + 1) * 5];
                    s0 += v0 * w0[0] + v1 * w1[0];
                    s1 += v0 * w0[1] + v1 * w1[1];
                    s2 += v0 * w0[2] + v1 * w1[2];
                    s3 += v0 * w0[3] + v1 * w1[3];
                    s4 += v0 * w0[4] + v1 * w1[4];
                }
                s0 = qsum(s0); s1 = qsum(s1); s2 = qsum(s2); s3 = qsum(s3); s4 = qsum(s4);
                if ((lane & 3) == 0) {
                    int rl = warp_m * 64 + mi * 16 + (lane >> 2) + half * 8;   // 0..127
                    float* d = &red[(rl * 4 + warp_n) * 5];
                    d[0] = s0; d[1] = s1; d[2] = s2; d[3] = s3; d[4] = s4;
                }
            }
        __syncthreads();
        if (tid < 128) {
            int chunk = n0 >> 7;
            float o0 = 0.f, o1 = 0.f, o2 = 0.f, o3 = 0.f, o4 = 0.f;
            #pragma unroll
            for (int wn = 0; wn < 4; wn++) {
                const float* p = &red[(tid * 4 + wn) * 5];
                o0 += p[0]; o1 += p[1]; o2 += p[2]; o3 += p[3]; o4 += p[4];
            }
            float* d = &g_part[step][chunk][(size_t)(m0 + tid) * 5];
            d[0] = o0; d[1] = o1; d[2] = o2; d[3] = o3; d[4] = o4;
        }
    } else if (n0 < 2048) {
        // ---- num head epilogue: CTA-reduced to 1 partial/row ----
        float* sw = (float*)smem;                 // [128]
        float* red = (float*)(smem + 1024);       // [128 rows][4 wn]
        for (int i = tid; i < 128; i += 256) sw[i] = w_num2[n0 - 1024 + i];
        __syncthreads();
        #pragma unroll
        for (int mi = 0; mi < 4; mi++)
            #pragma unroll
            for (int half = 0; half < 2; half++) {
                float s = 0.f;
                #pragma unroll
                for (int nj = 0; nj < 4; nj++) {
                    int nl = warp_n * 32 + nj * 8 + (lane & 3) * 2;
                    float2 b2 = *(const float2*)&g_bias[n0 + nl];
                    float v0 = gelu_f(acc[mi][nj][half * 2 + 0] + b2.x);
                    float v1 = gelu_f(acc[mi][nj][half * 2 + 1] + b2.y);
                    s += v0 * sw[nl] + v1 * sw[nl + 1];
                }
                s = qsum(s);
                if ((lane & 3) == 0) {
                    int rl = warp_m * 64 + mi * 16 + (lane >> 2) + half * 8;
                    red[rl * 4 + warp_n] = s;
                }
            }
        __syncthreads();
        if (tid < 128) {
            int chunk = (n0 - 1024) >> 7;
            float s = red[tid * 4] + red[tid * 4 + 1] + red[tid * 4 + 2] + red[tid * 4 + 3];
            g_pnum[step][chunk][m0 + tid] = s;
        }
    } else {
        // ---- gate epilogue: full GRU update for 128 rows x 32 hidden units ----
        int j0g = (n0 - 2048) >> 2;                    // global j base (multiple of 32)
        float* sh_hold = (float*)smem;                  // [128][33]
        float* sh_hnew = (float*)(smem + 17024);        // [128][33]

        // stage h_old tile [128][32] coalesced (1024 float4 / 256 thr = 4 each)
        #pragma unroll
        for (int it = 0; it < 4; it++) {
            int i4 = tid + it * 256;
            int r = i4 >> 3;
            int c4 = i4 & 7;
            float4 v = *(const float4*)(hin + (size_t)(m0 + r) * H + j0g + c4 * 4);
            float* d = &sh_hold[r * 33 + c4 * 4];
            d[0] = v.x; d[1] = v.y; d[2] = v.z; d[3] = v.w;
        }
        __syncthreads();

        bool compute = ((lane & 1) == 0);
        int jbase = warp_n * 8 + ((lane & 3) >> 1);
        int mbase = warp_m * 64 + (lane >> 2);
        #pragma unroll
        for (int nj = 0; nj < 4; nj++) {
            int n = n0 + warp_n * 32 + nj * 8 + (lane & 3) * 2;
            float2 b2 = *(const float2*)&g_bias[n];
            #pragma unroll
            for (int mi = 0; mi < 4; mi++) {
                float c0 = acc[mi][nj][0] + b2.x;
                float c1 = acc[mi][nj][1] + b2.y;
                float c2 = acc[mi][nj][2] + b2.x;
                float c3 = acc[mi][nj][3] + b2.y;
                float p0 = __shfl_xor_sync(0xffffffffu, c0, 1);
                float p1 = __shfl_xor_sync(0xffffffffu, c1, 1);
                float p2 = __shfl_xor_sync(0xffffffffu, c2, 1);
                float p3 = __shfl_xor_sync(0xffffffffu, c3, 1);
                if (compute) {
                    int jl = jbase + nj * 2;
                    int ml = mbase + mi * 16;
                    float rr = sigmoid_f(c0);
                    float zz = sigmoid_f(c1);
                    float nn = tanhf(p0 + rr * p1);
                    sh_hnew[ml * 33 + jl] = (1.f - zz) * nn + zz * sh_hold[ml * 33 + jl];
                    float rr2 = sigmoid_f(c2);
                    float zz2 = sigmoid_f(c3);
                    float nn2 = tanhf(p2 + rr2 * p3);
                    sh_hnew[(ml + 8) * 33 + jl] =
                        (1.f - zz2) * nn2 + zz2 * sh_hold[(ml + 8) * 33 + jl];
                }
            }
        }
        __syncthreads();

        // write h' fp32 + fp16 coalesced
        #pragma unroll
        for (int it = 0; it < 4; it++) {
            int i4 = tid + it * 256;
            int r = i4 >> 3;
            int c4 = i4 & 7;
            const float* s = &sh_hnew[r * 33 + c4 * 4];
            float4 v = make_float4(s[0], s[1], s[2], s[3]);
            size_t off = (size_t)(m0 + r) * H + j0g + c4 * 4;
            *(float4*)(hout + off) = v;
            *(uint2*)(Aout + off) = make_uint2(pkh2(v.x, v.y), pkh2(v.z, v.w));
        }
    }
}

// ======= final reduce: all steps' head partials -> ops/nums (one launch) =======
__global__ __launch_bounds__(128) void reduce_heads_kernel(
    const float* __restrict__ b_op2, const float* __restrict__ b_num2,
    float* __restrict__ ops, float* __restrict__ nums)
{
    int step = blockIdx.y;
    int b = blockIdx.x * 128 + threadIdx.x;   // over BB
    float s0 = b_op2[0], s1 = b_op2[1], s2 = b_op2[2], s3 = b_op2[3], s4 = b_op2[4];
    float sn = b_num2[0];
    #pragma unroll
    for (int k = 0; k < 8; k++) {
        const float* p = &g_part[step][k][(size_t)b * 5];
        s0 += p[0]; s1 += p[1]; s2 += p[2]; s3 += p[3]; s4 += p[4];
        sn += g_pnum[step][k][b];
    }
    float* o = ops + ((size_t)step * BB + b) * 5;
    o[0] = s0; o[1] = s1; o[2] = s2; o[3] = s3; o[4] = s4;
    nums[(size_t)step * BB + b] = sn;
}

extern "C" void kernel_launch(void* const* d_in, const int* in_sizes, int n_in,
                              void* d_out, int out_size) {
    const float* x      = (const float*)d_in[0];
    const float* w_op1  = (const float*)d_in[2];
    const float* b_op1  = (const float*)d_in[3];
    const float* w_op2  = (const float*)d_in[4];
    const float* b_op2  = (const float*)d_in[5];
    const float* w_num1 = (const float*)d_in[6];
    const float* b_num1 = (const float*)d_in[7];
    const float* w_num2 = (const float*)d_in[8];
    const float* b_num2 = (const float*)d_in[9];
    const float* w_ih   = (const float*)d_in[10];
    const float* b_ih   = (const float*)d_in[11];
    const float* w_hh   = (const float*)d_in[12];
    const float* b_hh   = (const float*)d_in[13];

    float* out = (float*)d_out;
    float* final_state = out;                       // [B,H]
    float* ops    = out + (size_t)BB * H;           // [8,B,5]
    float* nums   = ops + (size_t)NSTEPS * BB * 5;  // [8,B,1]
    float* states = nums + (size_t)NSTEPS * BB;     // [8,B,H]

    cudaFuncSetAttribute(gemm_mma_kernel, cudaFuncAttributeMaxDynamicSharedMemorySize, GEMM_SMEM);

    int prep_threads = NB * H + BB * H / 4;
    prep_kernel<<<(prep_threads + 255) / 256, 256>>>(w_op1, b_op1, w_num1, b_num1,
                                                     w_ih, b_ih, w_hh, b_hh, x, states);

    for (int s = 0; s < NSTEPS; s++) {
        const float* h = states + (size_t)s * BB * H;
        float* hnext = (s < NSTEPS - 1) ? states + (size_t)(s + 1) * BB * H : final_state;

        dim3 grid(NB / BN, BB / BM);
        gemm_mma_kernel<<<grid, 256, GEMM_SMEM>>>(s, h, hnext, w_op2, w_num2);
    }
    dim3 rgrid(BB / 128, NSTEPS);
    reduce_heads_kernel<<<rgrid, 128>>>(b_op2, b_num2, ops, nums);
}